// round 7
// baseline (speedup 1.0000x reference)
#include <cuda_runtime.h>
#include <cuda_bf16.h>
#include <math.h>

// ---------------------------------------------------------------------------
// DKVMN: B=64, L=200, D=128, M=50, FIX=512. Rows = 12800.
//   k = k_emb[q]@W1+b1            gemm64x64<512,1,0>
//   v = v_emb[q+1e4 r]@W2+b2      gemm64x64<512,2,0>
//   w = softmax(k@Mk^T)           wsoftmax
//   e = sigmoid(v@We+be)          gemm64x64<128,0,1>
//   a = tanh(v@Wa+ba)             gemm64x64<128,0,2>
//   scan: barrier-free; warp owns (b, 32-d chunk), lane owns d + all 50 m
//   p = sigmoid(tanh([reads|k]@Wf+bf)@Wp+bp)   head (64x128 tile)
// ---------------------------------------------------------------------------

#define NROWS 12800

__device__ float g_k[NROWS * 128];
__device__ float g_v[NROWS * 128];
__device__ float g_e[NROWS * 128];
__device__ float g_a[NROWS * 128];
__device__ float g_reads[NROWS * 128];
__device__ float g_w[NROWS * 64];   // pitch 64, 50 valid

__device__ __forceinline__ float fast_tanh(float x) {
    float y;
    asm("tanh.approx.f32 %0, %1;" : "=f"(y) : "f"(x));
    return y;
}
__device__ __forceinline__ float fast_sig(float x) {
    return 0.5f * fast_tanh(0.5f * x) + 0.5f;
}

// ---------------------------------------------------------------------------
// 64x64 tile GEMM, 64 threads, 8x8 per thread, double-buffered BK=16.
// grid = (2 col-halves, 200 row-tiles).
// IDX: 0 direct (lda=128), 1 gather q (lda=512), 2 gather q+10000r (lda=512)
// ACT: 0 none, 1 sigmoid, 2 tanh
// ---------------------------------------------------------------------------
template <int KDIM, int IDX, int ACT>
__global__ __launch_bounds__(64) void gemm64x64_kernel(
    const float* __restrict__ A, const int* __restrict__ qi,
    const int* __restrict__ ri, const float* __restrict__ W,
    const float* __restrict__ bias, float* __restrict__ C)
{
    __shared__ float As[2][16][68];   // [kk][row] transposed
    __shared__ float Bs[2][16][68];   // [kk][col]

    const int t  = threadIdx.x;
    const int nb = blockIdx.x;        // column half (0/1)
    const int mb = blockIdx.y;        // 64-row tile
    const int cx = t & 7;             // 8 col groups of 8
    const int ry = t >> 3;            // 8 row groups of 8
    const int c4 = t & 3;             // A-load col slot
    const int r0 = t >> 2;            // A-load base row (0..15)

    const float* aptr[4];
#pragma unroll
    for (int u = 0; u < 4; ++u) {
        int rr = mb * 64 + r0 + u * 16;
        size_t arow;
        if (IDX == 1)      arow = (size_t)qi[rr];
        else if (IDX == 2) arow = (size_t)qi[rr] + (size_t)10000 * (size_t)ri[rr];
        else               arow = (size_t)rr;
        aptr[u] = A + arow * (size_t)((IDX == 0) ? 128 : 512);
    }
    const float* Wb = W + nb * 64;

    float4 ar[4], br[4];
    auto ldA = [&](int kt) {
#pragma unroll
        for (int u = 0; u < 4; ++u)
            ar[u] = *reinterpret_cast<const float4*>(aptr[u] + kt * 16 + c4 * 4);
    };
    auto ldB = [&](int kt) {
#pragma unroll
        for (int u = 0; u < 4; ++u) {
            int e = t + u * 64;
            int rr = e >> 4, cb = e & 15;
            br[u] = *reinterpret_cast<const float4*>(Wb + (size_t)(kt * 16 + rr) * 128 + cb * 4);
        }
    };
    auto stAB = [&](int buf) {
#pragma unroll
        for (int u = 0; u < 4; ++u) {
            int row = r0 + u * 16;
            As[buf][c4 * 4 + 0][row] = ar[u].x;
            As[buf][c4 * 4 + 1][row] = ar[u].y;
            As[buf][c4 * 4 + 2][row] = ar[u].z;
            As[buf][c4 * 4 + 3][row] = ar[u].w;
        }
#pragma unroll
        for (int u = 0; u < 4; ++u) {
            int e = t + u * 64;
            int rr = e >> 4, cb = e & 15;
            *reinterpret_cast<float4*>(&Bs[buf][rr][cb * 4]) = br[u];
        }
    };

    float acc[8][8];
#pragma unroll
    for (int i = 0; i < 8; i++)
#pragma unroll
        for (int j = 0; j < 8; j++) acc[i][j] = 0.f;

    constexpr int NT = KDIM / 16;
    ldA(0); ldB(0); stAB(0);
    __syncthreads();

#pragma unroll 1
    for (int kt = 0; kt < NT; ++kt) {
        const int cur = kt & 1, nxt = cur ^ 1;
        if (kt + 1 < NT) { ldA(kt + 1); ldB(kt + 1); }
#pragma unroll
        for (int kk = 0; kk < 16; ++kk) {
            float4 a0 = *reinterpret_cast<const float4*>(&As[cur][kk][ry * 8]);
            float4 a1 = *reinterpret_cast<const float4*>(&As[cur][kk][ry * 8 + 4]);
            float4 b0 = *reinterpret_cast<const float4*>(&Bs[cur][kk][cx * 8]);
            float4 b1 = *reinterpret_cast<const float4*>(&Bs[cur][kk][cx * 8 + 4]);
            float aa[8] = {a0.x, a0.y, a0.z, a0.w, a1.x, a1.y, a1.z, a1.w};
            float bb[8] = {b0.x, b0.y, b0.z, b0.w, b1.x, b1.y, b1.z, b1.w};
#pragma unroll
            for (int i = 0; i < 8; ++i)
#pragma unroll
                for (int j = 0; j < 8; ++j)
                    acc[i][j] = fmaf(aa[i], bb[j], acc[i][j]);
        }
        if (kt + 1 < NT) stAB(nxt);
        __syncthreads();
    }

    // epilogue
#pragma unroll
    for (int i = 0; i < 8; ++i) {
        size_t row = (size_t)(mb * 64 + ry * 8 + i);
        float o[8];
#pragma unroll
        for (int j = 0; j < 8; ++j) {
            int c = nb * 64 + cx * 8 + j;
            float vv = acc[i][j] + bias[c];
            if (ACT == 1) vv = fast_sig(vv);
            if (ACT == 2) vv = fast_tanh(vv);
            o[j] = vv;
        }
        float* dst = C + row * 128 + nb * 64 + cx * 8;
        *reinterpret_cast<float4*>(dst)     = make_float4(o[0], o[1], o[2], o[3]);
        *reinterpret_cast<float4*>(dst + 4) = make_float4(o[4], o[5], o[6], o[7]);
    }
}

// ---------------------------------------------------------------------------
// head: 64x128 tile, 128 threads, 8x8 per thread, K=256 ([reads|k] concat).
// Fused p = sigmoid(tanh(f) . Wp + bp).
// ---------------------------------------------------------------------------
__global__ __launch_bounds__(128) void head_kernel(
    const float* __restrict__ reads, const float* __restrict__ k,
    const float* __restrict__ Wf, const float* __restrict__ bf,
    const float* __restrict__ Wp, const float* __restrict__ bp,
    float* __restrict__ out)
{
    __shared__ float As[2][16][68];    // [kk][row 64]
    __shared__ float Bs[2][16][132];   // [kk][col 128]
    __shared__ float pbuf[64][17];

    const int t  = threadIdx.x;
    const int mb = blockIdx.x;
    const int cx = t & 15;
    const int ry = t >> 4;
    const int lrow = t >> 1;           // A-load row (0..63)
    const int c4b  = (t & 1) * 2;      // A-load slot base

    const float* aR = reads + (size_t)(mb * 64 + lrow) * 128;
    const float* aK = k     + (size_t)(mb * 64 + lrow) * 128;

    float4 ar[2], br[4];
    auto ldA = [&](int kt) {
#pragma unroll
        for (int u = 0; u < 2; ++u) {
            const float* base = (kt < 8) ? (aR + kt * 16) : (aK + (kt - 8) * 16);
            ar[u] = *reinterpret_cast<const float4*>(base + (c4b + u) * 4);
        }
    };
    auto ldB = [&](int kt) {
#pragma unroll
        for (int u = 0; u < 4; ++u) {
            int e = t + u * 128;
            int rr = e >> 5, cb = e & 31;
            br[u] = *reinterpret_cast<const float4*>(Wf + (size_t)(kt * 16 + rr) * 128 + cb * 4);
        }
    };
    auto stAB = [&](int buf) {
#pragma unroll
        for (int u = 0; u < 2; ++u) {
            int kkb = (c4b + u) * 4;
            As[buf][kkb + 0][lrow] = ar[u].x;
            As[buf][kkb + 1][lrow] = ar[u].y;
            As[buf][kkb + 2][lrow] = ar[u].z;
            As[buf][kkb + 3][lrow] = ar[u].w;
        }
#pragma unroll
        for (int u = 0; u < 4; ++u) {
            int e = t + u * 128;
            int rr = e >> 5, cb = e & 31;
            *reinterpret_cast<float4*>(&Bs[buf][rr][cb * 4]) = br[u];
        }
    };

    float acc[8][8];
#pragma unroll
    for (int i = 0; i < 8; i++)
#pragma unroll
        for (int j = 0; j < 8; j++) acc[i][j] = 0.f;

    ldA(0); ldB(0); stAB(0);
    __syncthreads();

#pragma unroll 1
    for (int kt = 0; kt < 16; ++kt) {
        const int cur = kt & 1, nxt = cur ^ 1;
        if (kt + 1 < 16) { ldA(kt + 1); ldB(kt + 1); }
#pragma unroll
        for (int kk = 0; kk < 16; ++kk) {
            float4 a0 = *reinterpret_cast<const float4*>(&As[cur][kk][ry * 8]);
            float4 a1 = *reinterpret_cast<const float4*>(&As[cur][kk][ry * 8 + 4]);
            float4 b0 = *reinterpret_cast<const float4*>(&Bs[cur][kk][cx * 8]);
            float4 b1 = *reinterpret_cast<const float4*>(&Bs[cur][kk][cx * 8 + 4]);
            float aa[8] = {a0.x, a0.y, a0.z, a0.w, a1.x, a1.y, a1.z, a1.w};
            float bb[8] = {b0.x, b0.y, b0.z, b0.w, b1.x, b1.y, b1.z, b1.w};
#pragma unroll
            for (int i = 0; i < 8; ++i)
#pragma unroll
                for (int j = 0; j < 8; ++j)
                    acc[i][j] = fmaf(aa[i], bb[j], acc[i][j]);
        }
        if (kt + 1 < 16) stAB(nxt);
        __syncthreads();
    }

    // fused epilogue: f = tanh(acc + bf); partial p-dot
#pragma unroll
    for (int i = 0; i < 8; ++i) {
        float pac = 0.f;
#pragma unroll
        for (int j = 0; j < 8; ++j) {
            int c = cx * 8 + j;
            float f = fast_tanh(acc[i][j] + bf[c]);
            pac = fmaf(f, Wp[c], pac);
        }
        pbuf[ry * 8 + i][cx] = pac;
    }
    __syncthreads();
    if (t < 64) {
        float s = bp[0];
#pragma unroll
        for (int x = 0; x < 16; ++x) s += pbuf[t][x];
        out[mb * 64 + t] = 1.f / (1.f + __expf(-s));
    }
}

// ---------------------------------------------------------------------------
// w = softmax(k @ Mk^T) : 32 rows/CTA, 128 threads (static smem).
// ---------------------------------------------------------------------------
__global__ __launch_bounds__(128) void wsoftmax_kernel(
    const float* __restrict__ K, const float* __restrict__ Mk,
    float* __restrict__ Wout)
{
    __shared__ float sm_k[32 * 132];
    __shared__ float sm_m[50 * 132];
    float4* kt4 = reinterpret_cast<float4*>(sm_k);   // pitch 33 float4
    float4* mk4 = reinterpret_cast<float4*>(sm_m);
    float*  lg  = sm_k;                              // reuse (pitch 52)

    const int t  = threadIdx.x;
    const int bi = blockIdx.x;

    for (int e = t; e < 32 * 32; e += 128) {
        int rw = e >> 5, c4 = e & 31;
        kt4[rw * 33 + c4] =
            *reinterpret_cast<const float4*>(K + ((size_t)(bi * 32 + rw)) * 128 + c4 * 4);
    }
    for (int e = t; e < 50 * 32; e += 128) {
        int m = e >> 5, c4 = e & 31;
        mk4[m * 33 + c4] = *reinterpret_cast<const float4*>(Mk + (size_t)m * 128 + c4 * 4);
    }
    __syncthreads();

    const int row = t >> 2;
    const int mg  = t & 3;
    const int m0  = (mg < 2) ? mg * 13 : 26 + (mg - 2) * 12;
    const int cnt = (mg < 2) ? 13 : 12;

    float s[13];
#pragma unroll
    for (int j = 0; j < 13; j++) s[j] = 0.f;

    for (int c4 = 0; c4 < 32; ++c4) {
        float4 kv = kt4[row * 33 + c4];
#pragma unroll
        for (int j = 0; j < 13; j++) {
            if (j < cnt) {
                float4 mv = mk4[(m0 + j) * 33 + c4];
                s[j] = fmaf(kv.x, mv.x, fmaf(kv.y, mv.y,
                        fmaf(kv.z, mv.z, fmaf(kv.w, mv.w, s[j]))));
            }
        }
    }
    __syncthreads();
#pragma unroll
    for (int j = 0; j < 13; j++)
        if (j < cnt) lg[row * 52 + m0 + j] = s[j];
    __syncthreads();

    if (t < 32) {
        float mx = -1e30f;
        for (int m = 0; m < 50; m++) mx = fmaxf(mx, lg[t * 52 + m]);
        float sum = 0.f;
        for (int m = 0; m < 50; m++) sum += __expf(lg[t * 52 + m] - mx);
        float inv = 1.f / sum;
        size_t ob = (size_t)(bi * 32 + t) * 64;
        for (int m = 0; m < 50; m++)
            Wout[ob + m] = __expf(lg[t * 52 + m] - mx) * inv;
    }
}

// ---------------------------------------------------------------------------
// Scan, barrier-free: grid 64 CTAs x 128 threads = 4 independent warps/CTA.
// Warp w of CTA b handles (batch b, d-chunk w). Lane owns d = w*32+lane and
// ALL 50 Mv[m][d] in registers. r_t reduction is per-lane (over registers).
// w[t] broadcast via compile-time-index shfl from 2 regs/lane. No barriers.
// ---------------------------------------------------------------------------
__global__ __launch_bounds__(128) void scan_kernel(
    const float* __restrict__ Wm, const float* __restrict__ E,
    const float* __restrict__ Aa, const float* __restrict__ Mv0,
    float* __restrict__ R)
{
    const int b    = blockIdx.x;
    const int wid  = threadIdx.x >> 5;
    const int lane = threadIdx.x & 31;
    const int d    = wid * 32 + lane;

    float mv[50];
#pragma unroll
    for (int m = 0; m < 50; ++m) mv[m] = Mv0[m * 128 + d];

    const size_t rowbase = (size_t)b * 200;
    const float* Ep = E  + rowbase * 128 + d;
    const float* Ap = Aa + rowbase * 128 + d;
    const float* Wp = Wm + rowbase * 64;
    float*       Rp = R  + rowbase * 128 + d;

    // prefetch step 0
    float w0 = Wp[lane];
    float w1 = (lane < 18) ? Wp[32 + lane] : 0.f;
    float ed = Ep[0];
    float ad = Ap[0];

#pragma unroll 1
    for (int tt = 0; tt < 200; ++tt) {
        float w0n = 0.f, w1n = 0.f, en = 0.f, an = 0.f;
        if (tt < 199) {
            const float* Wn = Wp + (size_t)(tt + 1) * 64;
            w0n = Wn[lane];
            w1n = (lane < 18) ? Wn[32 + lane] : 0.f;
            en  = Ep[(size_t)(tt + 1) * 128];
            an  = Ap[(size_t)(tt + 1) * 128];
        }

        float ac0 = 0.f, ac1 = 0.f, ac2 = 0.f, ac3 = 0.f;
#pragma unroll
        for (int m = 0; m < 50; ++m) {
            float wm = (m < 32) ? __shfl_sync(0xffffffffu, w0, m)
                                : __shfl_sync(0xffffffffu, w1, m - 32);
            float mvm = mv[m];
            if ((m & 3) == 0)      ac0 = fmaf(wm, mvm, ac0);
            else if ((m & 3) == 1) ac1 = fmaf(wm, mvm, ac1);
            else if ((m & 3) == 2) ac2 = fmaf(wm, mvm, ac2);
            else                   ac3 = fmaf(wm, mvm, ac3);
            mv[m] = fmaf(wm, fmaf(-mvm, ed, ad), mvm);
        }
        Rp[(size_t)tt * 128] = (ac0 + ac1) + (ac2 + ac3);

        w0 = w0n; w1 = w1n; ed = en; ad = an;
    }
}

// ---------------------------------------------------------------------------
extern "C" void kernel_launch(void* const* d_in, const int* in_sizes, int n_in,
                              void* d_out, int out_size)
{
    const int*   q     = (const int*)d_in[0];
    const int*   r     = (const int*)d_in[1];
    // d_in[2] = diff (unused)
    const float* k_emb = (const float*)d_in[3];
    const float* v_emb = (const float*)d_in[4];
    const float* W1 = (const float*)d_in[5];
    const float* b1 = (const float*)d_in[6];
    const float* W2 = (const float*)d_in[7];
    const float* b2 = (const float*)d_in[8];
    const float* Mk  = (const float*)d_in[9];
    const float* Mv0 = (const float*)d_in[10];
    const float* We = (const float*)d_in[11];
    const float* be = (const float*)d_in[12];
    const float* Wa = (const float*)d_in[13];
    const float* ba = (const float*)d_in[14];
    const float* Wf = (const float*)d_in[15];
    const float* bf = (const float*)d_in[16];
    const float* Wp = (const float*)d_in[17];
    const float* bp = (const float*)d_in[18];
    float* out = (float*)d_out;

    float *pk, *pv, *pe, *pa, *pr, *pw;
    cudaGetSymbolAddress((void**)&pk, g_k);
    cudaGetSymbolAddress((void**)&pv, g_v);
    cudaGetSymbolAddress((void**)&pe, g_e);
    cudaGetSymbolAddress((void**)&pa, g_a);
    cudaGetSymbolAddress((void**)&pr, g_reads);
    cudaGetSymbolAddress((void**)&pw, g_w);

    dim3 gg(2, 200);
    gemm64x64_kernel<512, 1, 0><<<gg, 64>>>(k_emb, q, r, W1, b1, pk);
    gemm64x64_kernel<512, 2, 0><<<gg, 64>>>(v_emb, q, r, W2, b2, pv);
    wsoftmax_kernel<<<400, 128>>>(pk, Mk, pw);
    gemm64x64_kernel<128, 0, 1><<<gg, 64>>>(pv, q, r, We, be, pe);
    gemm64x64_kernel<128, 0, 2><<<gg, 64>>>(pv, q, r, Wa, ba, pa);
    scan_kernel<<<64, 128>>>(pw, pe, pa, Mv0, pr);
    head_kernel<<<200, 128>>>(pr, pk, Wf, bf, Wp, bp, out);
}

// round 8
// speedup vs baseline: 1.3843x; 1.3843x over previous
#include <cuda_runtime.h>
#include <cuda_bf16.h>
#include <math.h>

// ---------------------------------------------------------------------------
// DKVMN: B=64, L=200, D=128, M=50, FIX=512. Rows = 12800.
//   k = k_emb[q]@W1+b1            gemm64x64<512,1,0>
//   v = v_emb[q+1e4 r]@W2+b2      gemm64x64<512,2,0>
//   w = softmax(k@Mk^T)           wsoftmax (compact pitch-50 output)
//   e = sigmoid(v@We+be)          gemm64x64<128,0,1>
//   a = tanh(v@Wa+ba)             gemm64x64<128,0,2>
//   scan: CTA=batch; w staged in smem (40KB); lane=d, 50 Mv in regs;
//         zero barriers/reductions in the time loop.
//   p = sigmoid(tanh([reads|k]@Wf+bf)@Wp+bp)   head (64x128 tile)
// ---------------------------------------------------------------------------

#define NROWS 12800

__device__ float g_k[NROWS * 128];
__device__ float g_v[NROWS * 128];
__device__ float g_e[NROWS * 128];
__device__ float g_a[NROWS * 128];
__device__ float g_reads[NROWS * 128];
__device__ float g_w[NROWS * 50];   // compact pitch 50

__device__ __forceinline__ float fast_tanh(float x) {
    float y;
    asm("tanh.approx.f32 %0, %1;" : "=f"(y) : "f"(x));
    return y;
}
__device__ __forceinline__ float fast_sig(float x) {
    return 0.5f * fast_tanh(0.5f * x) + 0.5f;
}

// ---------------------------------------------------------------------------
// 64x64 tile GEMM, 64 threads, 8x8 per thread, double-buffered BK=16.
// grid = (2 col-halves, 200 row-tiles).  [measured-best R5 configuration]
// ---------------------------------------------------------------------------
template <int KDIM, int IDX, int ACT>
__global__ __launch_bounds__(64) void gemm64x64_kernel(
    const float* __restrict__ A, const int* __restrict__ qi,
    const int* __restrict__ ri, const float* __restrict__ W,
    const float* __restrict__ bias, float* __restrict__ C)
{
    __shared__ float As[2][16][68];
    __shared__ float Bs[2][16][68];

    const int t  = threadIdx.x;
    const int nb = blockIdx.x;
    const int mb = blockIdx.y;
    const int cx = t & 7;
    const int ry = t >> 3;
    const int c4 = t & 3;
    const int r0 = t >> 2;

    const float* aptr[4];
#pragma unroll
    for (int u = 0; u < 4; ++u) {
        int rr = mb * 64 + r0 + u * 16;
        size_t arow;
        if (IDX == 1)      arow = (size_t)qi[rr];
        else if (IDX == 2) arow = (size_t)qi[rr] + (size_t)10000 * (size_t)ri[rr];
        else               arow = (size_t)rr;
        aptr[u] = A + arow * (size_t)((IDX == 0) ? 128 : 512);
    }
    const float* Wb = W + nb * 64;

    float4 ar[4], br[4];
    auto ldA = [&](int kt) {
#pragma unroll
        for (int u = 0; u < 4; ++u)
            ar[u] = *reinterpret_cast<const float4*>(aptr[u] + kt * 16 + c4 * 4);
    };
    auto ldB = [&](int kt) {
#pragma unroll
        for (int u = 0; u < 4; ++u) {
            int e = t + u * 64;
            int rr = e >> 4, cb = e & 15;
            br[u] = *reinterpret_cast<const float4*>(Wb + (size_t)(kt * 16 + rr) * 128 + cb * 4);
        }
    };
    auto stAB = [&](int buf) {
#pragma unroll
        for (int u = 0; u < 4; ++u) {
            int row = r0 + u * 16;
            As[buf][c4 * 4 + 0][row] = ar[u].x;
            As[buf][c4 * 4 + 1][row] = ar[u].y;
            As[buf][c4 * 4 + 2][row] = ar[u].z;
            As[buf][c4 * 4 + 3][row] = ar[u].w;
        }
#pragma unroll
        for (int u = 0; u < 4; ++u) {
            int e = t + u * 64;
            int rr = e >> 4, cb = e & 15;
            *reinterpret_cast<float4*>(&Bs[buf][rr][cb * 4]) = br[u];
        }
    };

    float acc[8][8];
#pragma unroll
    for (int i = 0; i < 8; i++)
#pragma unroll
        for (int j = 0; j < 8; j++) acc[i][j] = 0.f;

    constexpr int NT = KDIM / 16;
    ldA(0); ldB(0); stAB(0);
    __syncthreads();

#pragma unroll 1
    for (int kt = 0; kt < NT; ++kt) {
        const int cur = kt & 1, nxt = cur ^ 1;
        if (kt + 1 < NT) { ldA(kt + 1); ldB(kt + 1); }
#pragma unroll
        for (int kk = 0; kk < 16; ++kk) {
            float4 a0 = *reinterpret_cast<const float4*>(&As[cur][kk][ry * 8]);
            float4 a1 = *reinterpret_cast<const float4*>(&As[cur][kk][ry * 8 + 4]);
            float4 b0 = *reinterpret_cast<const float4*>(&Bs[cur][kk][cx * 8]);
            float4 b1 = *reinterpret_cast<const float4*>(&Bs[cur][kk][cx * 8 + 4]);
            float aa[8] = {a0.x, a0.y, a0.z, a0.w, a1.x, a1.y, a1.z, a1.w};
            float bb[8] = {b0.x, b0.y, b0.z, b0.w, b1.x, b1.y, b1.z, b1.w};
#pragma unroll
            for (int i = 0; i < 8; ++i)
#pragma unroll
                for (int j = 0; j < 8; ++j)
                    acc[i][j] = fmaf(aa[i], bb[j], acc[i][j]);
        }
        if (kt + 1 < NT) stAB(nxt);
        __syncthreads();
    }

#pragma unroll
    for (int i = 0; i < 8; ++i) {
        size_t row = (size_t)(mb * 64 + ry * 8 + i);
        float o[8];
#pragma unroll
        for (int j = 0; j < 8; ++j) {
            int c = nb * 64 + cx * 8 + j;
            float vv = acc[i][j] + bias[c];
            if (ACT == 1) vv = fast_sig(vv);
            if (ACT == 2) vv = fast_tanh(vv);
            o[j] = vv;
        }
        float* dst = C + row * 128 + nb * 64 + cx * 8;
        *reinterpret_cast<float4*>(dst)     = make_float4(o[0], o[1], o[2], o[3]);
        *reinterpret_cast<float4*>(dst + 4) = make_float4(o[4], o[5], o[6], o[7]);
    }
}

// ---------------------------------------------------------------------------
// head: 64x128 tile, 128 threads, 8x8 per thread, K=256 ([reads|k] concat).
// ---------------------------------------------------------------------------
__global__ __launch_bounds__(128) void head_kernel(
    const float* __restrict__ reads, const float* __restrict__ k,
    const float* __restrict__ Wf, const float* __restrict__ bf,
    const float* __restrict__ Wp, const float* __restrict__ bp,
    float* __restrict__ out)
{
    __shared__ float As[2][16][68];
    __shared__ float Bs[2][16][132];
    __shared__ float pbuf[64][17];

    const int t  = threadIdx.x;
    const int mb = blockIdx.x;
    const int cx = t & 15;
    const int ry = t >> 4;
    const int lrow = t >> 1;
    const int c4b  = (t & 1) * 2;

    const float* aR = reads + (size_t)(mb * 64 + lrow) * 128;
    const float* aK = k     + (size_t)(mb * 64 + lrow) * 128;

    float4 ar[2], br[4];
    auto ldA = [&](int kt) {
#pragma unroll
        for (int u = 0; u < 2; ++u) {
            const float* base = (kt < 8) ? (aR + kt * 16) : (aK + (kt - 8) * 16);
            ar[u] = *reinterpret_cast<const float4*>(base + (c4b + u) * 4);
        }
    };
    auto ldB = [&](int kt) {
#pragma unroll
        for (int u = 0; u < 4; ++u) {
            int e = t + u * 128;
            int rr = e >> 5, cb = e & 31;
            br[u] = *reinterpret_cast<const float4*>(Wf + (size_t)(kt * 16 + rr) * 128 + cb * 4);
        }
    };
    auto stAB = [&](int buf) {
#pragma unroll
        for (int u = 0; u < 2; ++u) {
            int kkb = (c4b + u) * 4;
            As[buf][kkb + 0][lrow] = ar[u].x;
            As[buf][kkb + 1][lrow] = ar[u].y;
            As[buf][kkb + 2][lrow] = ar[u].z;
            As[buf][kkb + 3][lrow] = ar[u].w;
        }
#pragma unroll
        for (int u = 0; u < 4; ++u) {
            int e = t + u * 128;
            int rr = e >> 5, cb = e & 31;
            *reinterpret_cast<float4*>(&Bs[buf][rr][cb * 4]) = br[u];
        }
    };

    float acc[8][8];
#pragma unroll
    for (int i = 0; i < 8; i++)
#pragma unroll
        for (int j = 0; j < 8; j++) acc[i][j] = 0.f;

    ldA(0); ldB(0); stAB(0);
    __syncthreads();

#pragma unroll 1
    for (int kt = 0; kt < 16; ++kt) {
        const int cur = kt & 1, nxt = cur ^ 1;
        if (kt + 1 < 16) { ldA(kt + 1); ldB(kt + 1); }
#pragma unroll
        for (int kk = 0; kk < 16; ++kk) {
            float4 a0 = *reinterpret_cast<const float4*>(&As[cur][kk][ry * 8]);
            float4 a1 = *reinterpret_cast<const float4*>(&As[cur][kk][ry * 8 + 4]);
            float4 b0 = *reinterpret_cast<const float4*>(&Bs[cur][kk][cx * 8]);
            float4 b1 = *reinterpret_cast<const float4*>(&Bs[cur][kk][cx * 8 + 4]);
            float aa[8] = {a0.x, a0.y, a0.z, a0.w, a1.x, a1.y, a1.z, a1.w};
            float bb[8] = {b0.x, b0.y, b0.z, b0.w, b1.x, b1.y, b1.z, b1.w};
#pragma unroll
            for (int i = 0; i < 8; ++i)
#pragma unroll
                for (int j = 0; j < 8; ++j)
                    acc[i][j] = fmaf(aa[i], bb[j], acc[i][j]);
        }
        if (kt + 1 < 16) stAB(nxt);
        __syncthreads();
    }

#pragma unroll
    for (int i = 0; i < 8; ++i) {
        float pac = 0.f;
#pragma unroll
        for (int j = 0; j < 8; ++j) {
            int c = cx * 8 + j;
            float f = fast_tanh(acc[i][j] + bf[c]);
            pac = fmaf(f, Wp[c], pac);
        }
        pbuf[ry * 8 + i][cx] = pac;
    }
    __syncthreads();
    if (t < 64) {
        float s = bp[0];
#pragma unroll
        for (int x = 0; x < 16; ++x) s += pbuf[t][x];
        out[mb * 64 + t] = 1.f / (1.f + __expf(-s));
    }
}

// ---------------------------------------------------------------------------
// w = softmax(k @ Mk^T) : 32 rows/CTA, 128 threads. COMPACT pitch-50 output.
// ---------------------------------------------------------------------------
__global__ __launch_bounds__(128) void wsoftmax_kernel(
    const float* __restrict__ K, const float* __restrict__ Mk,
    float* __restrict__ Wout)
{
    __shared__ float sm_k[32 * 132];
    __shared__ float sm_m[50 * 132];
    float4* kt4 = reinterpret_cast<float4*>(sm_k);
    float4* mk4 = reinterpret_cast<float4*>(sm_m);
    float*  lg  = sm_k;

    const int t  = threadIdx.x;
    const int bi = blockIdx.x;

    for (int e = t; e < 32 * 32; e += 128) {
        int rw = e >> 5, c4 = e & 31;
        kt4[rw * 33 + c4] =
            *reinterpret_cast<const float4*>(K + ((size_t)(bi * 32 + rw)) * 128 + c4 * 4);
    }
    for (int e = t; e < 50 * 32; e += 128) {
        int m = e >> 5, c4 = e & 31;
        mk4[m * 33 + c4] = *reinterpret_cast<const float4*>(Mk + (size_t)m * 128 + c4 * 4);
    }
    __syncthreads();

    const int row = t >> 2;
    const int mg  = t & 3;
    const int m0  = (mg < 2) ? mg * 13 : 26 + (mg - 2) * 12;
    const int cnt = (mg < 2) ? 13 : 12;

    float s[13];
#pragma unroll
    for (int j = 0; j < 13; j++) s[j] = 0.f;

    for (int c4 = 0; c4 < 32; ++c4) {
        float4 kv = kt4[row * 33 + c4];
#pragma unroll
        for (int j = 0; j < 13; j++) {
            if (j < cnt) {
                float4 mv = mk4[(m0 + j) * 33 + c4];
                s[j] = fmaf(kv.x, mv.x, fmaf(kv.y, mv.y,
                        fmaf(kv.z, mv.z, fmaf(kv.w, mv.w, s[j]))));
            }
        }
    }
    __syncthreads();
#pragma unroll
    for (int j = 0; j < 13; j++)
        if (j < cnt) lg[row * 52 + m0 + j] = s[j];
    __syncthreads();

    if (t < 32) {
        float mx = -1e30f;
        for (int m = 0; m < 50; m++) mx = fmaxf(mx, lg[t * 52 + m]);
        float sum = 0.f;
        for (int m = 0; m < 50; m++) sum += __expf(lg[t * 52 + m] - mx);
        float inv = 1.f / sum;
        size_t ob = (size_t)(bi * 32 + t) * 50;
        for (int m = 0; m < 50; m++)
            Wout[ob + m] = __expf(lg[t * 52 + m] - mx) * inv;
    }
}

// ---------------------------------------------------------------------------
// Scan: CTA = batch (64 CTAs, 128 threads). Lane owns d = threadIdx.x and all
// 50 Mv[m][d] in registers. Whole w sequence (200x50 = 40KB) staged in smem:
// per-step w access = uniform LDS broadcast, hoistable (addr indep of data).
// No barriers / reductions in the time loop. E/A prefetched 1 step ahead.
// ---------------------------------------------------------------------------
__global__ __launch_bounds__(128) void scan_kernel(
    const float* __restrict__ Wm, const float* __restrict__ E,
    const float* __restrict__ Aa, const float* __restrict__ Mv0,
    float* __restrict__ R)
{
    __shared__ float ws[200 * 50];    // 40 KB

    const int b = blockIdx.x;
    const int d = threadIdx.x;        // 0..127

    // stage w for this batch: 10000 floats = 2500 float4
    {
        const float4* src = reinterpret_cast<const float4*>(Wm + (size_t)b * 10000);
        float4* dst = reinterpret_cast<float4*>(ws);
        for (int i = d; i < 2500; i += 128) dst[i] = src[i];
    }

    float mv[50];
#pragma unroll
    for (int m = 0; m < 50; ++m) mv[m] = Mv0[m * 128 + d];
    __syncthreads();

    const size_t rowbase = (size_t)b * 200;
    const float* Ep = E  + rowbase * 128 + d;
    const float* Ap = Aa + rowbase * 128 + d;
    float*       Rp = R  + rowbase * 128 + d;

    float ed = Ep[0];
    float ad = Ap[0];

#pragma unroll 2
    for (int tt = 0; tt < 200; ++tt) {
        float en = 0.f, an = 0.f;
        if (tt < 199) {
            en = Ep[(size_t)(tt + 1) * 128];
            an = Ap[(size_t)(tt + 1) * 128];
        }

        const float* wrow = ws + tt * 50;
        float ac0 = 0.f, ac1 = 0.f, ac2 = 0.f, ac3 = 0.f;
#pragma unroll
        for (int m = 0; m < 50; ++m) {
            float wm = wrow[m];                 // uniform LDS broadcast
            float mvm = mv[m];
            if ((m & 3) == 0)      ac0 = fmaf(wm, mvm, ac0);
            else if ((m & 3) == 1) ac1 = fmaf(wm, mvm, ac1);
            else if ((m & 3) == 2) ac2 = fmaf(wm, mvm, ac2);
            else                   ac3 = fmaf(wm, mvm, ac3);
            mv[m] = fmaf(wm, fmaf(-mvm, ed, ad), mvm);
        }
        Rp[(size_t)tt * 128] = (ac0 + ac1) + (ac2 + ac3);

        ed = en; ad = an;
    }
}

// ---------------------------------------------------------------------------
extern "C" void kernel_launch(void* const* d_in, const int* in_sizes, int n_in,
                              void* d_out, int out_size)
{
    const int*   q     = (const int*)d_in[0];
    const int*   r     = (const int*)d_in[1];
    // d_in[2] = diff (unused)
    const float* k_emb = (const float*)d_in[3];
    const float* v_emb = (const float*)d_in[4];
    const float* W1 = (const float*)d_in[5];
    const float* b1 = (const float*)d_in[6];
    const float* W2 = (const float*)d_in[7];
    const float* b2 = (const float*)d_in[8];
    const float* Mk  = (const float*)d_in[9];
    const float* Mv0 = (const float*)d_in[10];
    const float* We = (const float*)d_in[11];
    const float* be = (const float*)d_in[12];
    const float* Wa = (const float*)d_in[13];
    const float* ba = (const float*)d_in[14];
    const float* Wf = (const float*)d_in[15];
    const float* bf = (const float*)d_in[16];
    const float* Wp = (const float*)d_in[17];
    const float* bp = (const float*)d_in[18];
    float* out = (float*)d_out;

    float *pk, *pv, *pe, *pa, *pr, *pw;
    cudaGetSymbolAddress((void**)&pk, g_k);
    cudaGetSymbolAddress((void**)&pv, g_v);
    cudaGetSymbolAddress((void**)&pe, g_e);
    cudaGetSymbolAddress((void**)&pa, g_a);
    cudaGetSymbolAddress((void**)&pr, g_reads);
    cudaGetSymbolAddress((void**)&pw, g_w);

    dim3 gg(2, 200);
    gemm64x64_kernel<512, 1, 0><<<gg, 64>>>(k_emb, q, r, W1, b1, pk);
    gemm64x64_kernel<512, 2, 0><<<gg, 64>>>(v_emb, q, r, W2, b2, pv);
    wsoftmax_kernel<<<400, 128>>>(pk, Mk, pw);
    gemm64x64_kernel<128, 0, 1><<<gg, 64>>>(pv, q, r, We, be, pe);
    gemm64x64_kernel<128, 0, 2><<<gg, 64>>>(pv, q, r, Wa, ba, pa);
    scan_kernel<<<64, 128>>>(pw, pe, pa, Mv0, pr);
    head_kernel<<<200, 128>>>(pr, pk, Wf, bf, Wp, bp, out);
}

// round 9
// speedup vs baseline: 1.6170x; 1.1681x over previous
#include <cuda_runtime.h>
#include <cuda_bf16.h>
#include <math.h>

// ---------------------------------------------------------------------------
// DKVMN: B=64, L=200, D=128, M=50, FIX=512. Rows = 12800.
//   kv_kernel (z=0): k = k_emb[q]@W1+b1        (z=1): v = v_emb[q+1e4r]@W2+b2
//   wsoftmax : w = softmax(k@Mk^T)  (compact pitch-50)
//   ea_kernel (z=0): e = sigmoid(v@We+be)      (z=1): a = tanh(v@Wa+ba)
//   scan : CTA=batch; w staged in smem; lane=d, 50 Mv in regs; no barriers.
//   head : p = sigmoid(tanh([reads|k]@Wf+bf)@Wp+bp)
// GEMMs: 64x64 tile, 64 threads, 8x8/thread, double-buffered BK=16.
// Independent GEMMs share one launch via blockIdx.z -> 800 CTAs (occ 2x).
// ---------------------------------------------------------------------------

#define NROWS 12800

__device__ float g_k[NROWS * 128];
__device__ float g_v[NROWS * 128];
__device__ float g_e[NROWS * 128];
__device__ float g_a[NROWS * 128];
__device__ float g_reads[NROWS * 128];
__device__ float g_w[NROWS * 50];   // compact pitch 50

__device__ __forceinline__ float fast_tanh(float x) {
    float y;
    asm("tanh.approx.f32 %0, %1;" : "=f"(y) : "f"(x));
    return y;
}
__device__ __forceinline__ float fast_sig(float x) {
    return 0.5f * fast_tanh(0.5f * x) + 0.5f;
}

// ---------------------------------------------------------------------------
// Core 64x64 mainloop (device function). aptr[u]: row base pointers.
// ---------------------------------------------------------------------------
template <int NT>
__device__ __forceinline__ void mm_core(
    const float* const (&aptr)[4], const float* __restrict__ Wb,
    float (&acc)[8][8], float (*As)[16][68], float (*Bs)[16][68],
    int t, int c4, int r0)
{
    float4 ar[4], br[4];
    auto ldA = [&](int kt) {
#pragma unroll
        for (int u = 0; u < 4; ++u)
            ar[u] = *reinterpret_cast<const float4*>(aptr[u] + kt * 16 + c4 * 4);
    };
    auto ldB = [&](int kt) {
#pragma unroll
        for (int u = 0; u < 4; ++u) {
            int e = t + u * 64;
            int rr = e >> 4, cb = e & 15;
            br[u] = *reinterpret_cast<const float4*>(Wb + (size_t)(kt * 16 + rr) * 128 + cb * 4);
        }
    };
    auto stAB = [&](int buf) {
#pragma unroll
        for (int u = 0; u < 4; ++u) {
            int row = r0 + u * 16;
            As[buf][c4 * 4 + 0][row] = ar[u].x;
            As[buf][c4 * 4 + 1][row] = ar[u].y;
            As[buf][c4 * 4 + 2][row] = ar[u].z;
            As[buf][c4 * 4 + 3][row] = ar[u].w;
        }
#pragma unroll
        for (int u = 0; u < 4; ++u) {
            int e = t + u * 64;
            int rr = e >> 4, cb = e & 15;
            *reinterpret_cast<float4*>(&Bs[buf][rr][cb * 4]) = br[u];
        }
    };

    const int cx = t & 7, ry = t >> 3;

    ldA(0); ldB(0); stAB(0);
    __syncthreads();

#pragma unroll 1
    for (int kt = 0; kt < NT; ++kt) {
        const int cur = kt & 1, nxt = cur ^ 1;
        if (kt + 1 < NT) { ldA(kt + 1); ldB(kt + 1); }
#pragma unroll
        for (int kk = 0; kk < 16; ++kk) {
            float4 a0 = *reinterpret_cast<const float4*>(&As[cur][kk][ry * 8]);
            float4 a1 = *reinterpret_cast<const float4*>(&As[cur][kk][ry * 8 + 4]);
            float4 b0 = *reinterpret_cast<const float4*>(&Bs[cur][kk][cx * 8]);
            float4 b1 = *reinterpret_cast<const float4*>(&Bs[cur][kk][cx * 8 + 4]);
            float aa[8] = {a0.x, a0.y, a0.z, a0.w, a1.x, a1.y, a1.z, a1.w};
            float bb[8] = {b0.x, b0.y, b0.z, b0.w, b1.x, b1.y, b1.z, b1.w};
#pragma unroll
            for (int i = 0; i < 8; ++i)
#pragma unroll
                for (int j = 0; j < 8; ++j)
                    acc[i][j] = fmaf(aa[i], bb[j], acc[i][j]);
        }
        if (kt + 1 < NT) stAB(nxt);
        __syncthreads();
    }
}

// ---------------------------------------------------------------------------
// kv_kernel: grid (2, 200, 2). z=0: k path; z=1: v path. K=512 gather GEMM.
// ---------------------------------------------------------------------------
__global__ __launch_bounds__(64) void kv_kernel(
    const float* __restrict__ k_emb, const float* __restrict__ v_emb,
    const int* __restrict__ qi, const int* __restrict__ ri,
    const float* __restrict__ W1, const float* __restrict__ b1,
    const float* __restrict__ W2, const float* __restrict__ b2,
    float* __restrict__ gk, float* __restrict__ gv)
{
    __shared__ float As[2][16][68];
    __shared__ float Bs[2][16][68];

    const int t  = threadIdx.x;
    const int nb = blockIdx.x;
    const int mb = blockIdx.y;
    const int z  = blockIdx.z;
    const int cx = t & 7, ry = t >> 3;
    const int c4 = t & 3, r0 = t >> 2;

    const float* emb  = z ? v_emb : k_emb;
    const float* W    = z ? W2 : W1;
    const float* bias = z ? b2 : b1;
    float*       C    = z ? gv : gk;

    const float* aptr[4];
#pragma unroll
    for (int u = 0; u < 4; ++u) {
        int rr = mb * 64 + r0 + u * 16;
        size_t arow = (size_t)qi[rr];
        if (z) arow += (size_t)10000 * (size_t)ri[rr];
        aptr[u] = emb + arow * 512;
    }
    const float* Wb = W + nb * 64;

    float acc[8][8];
#pragma unroll
    for (int i = 0; i < 8; i++)
#pragma unroll
        for (int j = 0; j < 8; j++) acc[i][j] = 0.f;

    mm_core<32>(aptr, Wb, acc, As, Bs, t, c4, r0);

#pragma unroll
    for (int i = 0; i < 8; ++i) {
        size_t row = (size_t)(mb * 64 + ry * 8 + i);
        float o[8];
#pragma unroll
        for (int j = 0; j < 8; ++j)
            o[j] = acc[i][j] + bias[nb * 64 + cx * 8 + j];
        float* dst = C + row * 128 + nb * 64 + cx * 8;
        *reinterpret_cast<float4*>(dst)     = make_float4(o[0], o[1], o[2], o[3]);
        *reinterpret_cast<float4*>(dst + 4) = make_float4(o[4], o[5], o[6], o[7]);
    }
}

// ---------------------------------------------------------------------------
// ea_kernel: grid (2, 200, 2). z=0: e = sigmoid(v@We+be); z=1: a = tanh(v@Wa+ba)
// ---------------------------------------------------------------------------
__global__ __launch_bounds__(64) void ea_kernel(
    const float* __restrict__ V,
    const float* __restrict__ We, const float* __restrict__ be,
    const float* __restrict__ Wa, const float* __restrict__ ba,
    float* __restrict__ ge, float* __restrict__ ga)
{
    __shared__ float As[2][16][68];
    __shared__ float Bs[2][16][68];

    const int t  = threadIdx.x;
    const int nb = blockIdx.x;
    const int mb = blockIdx.y;
    const int z  = blockIdx.z;
    const int cx = t & 7, ry = t >> 3;
    const int c4 = t & 3, r0 = t >> 2;

    const float* W    = z ? Wa : We;
    const float* bias = z ? ba : be;
    float*       C    = z ? ga : ge;

    const float* aptr[4];
#pragma unroll
    for (int u = 0; u < 4; ++u) {
        int rr = mb * 64 + r0 + u * 16;
        aptr[u] = V + (size_t)rr * 128;
    }
    const float* Wb = W + nb * 64;

    float acc[8][8];
#pragma unroll
    for (int i = 0; i < 8; i++)
#pragma unroll
        for (int j = 0; j < 8; j++) acc[i][j] = 0.f;

    mm_core<8>(aptr, Wb, acc, As, Bs, t, c4, r0);

#pragma unroll
    for (int i = 0; i < 8; ++i) {
        size_t row = (size_t)(mb * 64 + ry * 8 + i);
        float o[8];
#pragma unroll
        for (int j = 0; j < 8; ++j) {
            float vv = acc[i][j] + bias[nb * 64 + cx * 8 + j];
            o[j] = z ? fast_tanh(vv) : fast_sig(vv);
        }
        float* dst = C + row * 128 + nb * 64 + cx * 8;
        *reinterpret_cast<float4*>(dst)     = make_float4(o[0], o[1], o[2], o[3]);
        *reinterpret_cast<float4*>(dst + 4) = make_float4(o[4], o[5], o[6], o[7]);
    }
}

// ---------------------------------------------------------------------------
// head: 64x128 tile, 128 threads, 8x8 per thread, K=256 ([reads|k] concat).
// ---------------------------------------------------------------------------
__global__ __launch_bounds__(128) void head_kernel(
    const float* __restrict__ reads, const float* __restrict__ k,
    const float* __restrict__ Wf, const float* __restrict__ bf,
    const float* __restrict__ Wp, const float* __restrict__ bp,
    float* __restrict__ out)
{
    __shared__ float As[2][16][68];
    __shared__ float Bs[2][16][132];
    __shared__ float pbuf[64][17];

    const int t  = threadIdx.x;
    const int mb = blockIdx.x;
    const int cx = t & 15;
    const int ry = t >> 4;
    const int lrow = t >> 1;
    const int c4b  = (t & 1) * 2;

    const float* aR = reads + (size_t)(mb * 64 + lrow) * 128;
    const float* aK = k     + (size_t)(mb * 64 + lrow) * 128;

    float4 ar[2], br[4];
    auto ldA = [&](int kt) {
#pragma unroll
        for (int u = 0; u < 2; ++u) {
            const float* base = (kt < 8) ? (aR + kt * 16) : (aK + (kt - 8) * 16);
            ar[u] = *reinterpret_cast<const float4*>(base + (c4b + u) * 4);
        }
    };
    auto ldB = [&](int kt) {
#pragma unroll
        for (int u = 0; u < 4; ++u) {
            int e = t + u * 128;
            int rr = e >> 5, cb = e & 31;
            br[u] = *reinterpret_cast<const float4*>(Wf + (size_t)(kt * 16 + rr) * 128 + cb * 4);
        }
    };
    auto stAB = [&](int buf) {
#pragma unroll
        for (int u = 0; u < 2; ++u) {
            int kkb = (c4b + u) * 4;
            As[buf][kkb + 0][lrow] = ar[u].x;
            As[buf][kkb + 1][lrow] = ar[u].y;
            As[buf][kkb + 2][lrow] = ar[u].z;
            As[buf][kkb + 3][lrow] = ar[u].w;
        }
#pragma unroll
        for (int u = 0; u < 4; ++u) {
            int e = t + u * 128;
            int rr = e >> 5, cb = e & 31;
            *reinterpret_cast<float4*>(&Bs[buf][rr][cb * 4]) = br[u];
        }
    };

    float acc[8][8];
#pragma unroll
    for (int i = 0; i < 8; i++)
#pragma unroll
        for (int j = 0; j < 8; j++) acc[i][j] = 0.f;

    ldA(0); ldB(0); stAB(0);
    __syncthreads();

#pragma unroll 1
    for (int kt = 0; kt < 16; ++kt) {
        const int cur = kt & 1, nxt = cur ^ 1;
        if (kt + 1 < 16) { ldA(kt + 1); ldB(kt + 1); }
#pragma unroll
        for (int kk = 0; kk < 16; ++kk) {
            float4 a0 = *reinterpret_cast<const float4*>(&As[cur][kk][ry * 8]);
            float4 a1 = *reinterpret_cast<const float4*>(&As[cur][kk][ry * 8 + 4]);
            float4 b0 = *reinterpret_cast<const float4*>(&Bs[cur][kk][cx * 8]);
            float4 b1 = *reinterpret_cast<const float4*>(&Bs[cur][kk][cx * 8 + 4]);
            float aa[8] = {a0.x, a0.y, a0.z, a0.w, a1.x, a1.y, a1.z, a1.w};
            float bb[8] = {b0.x, b0.y, b0.z, b0.w, b1.x, b1.y, b1.z, b1.w};
#pragma unroll
            for (int i = 0; i < 8; ++i)
#pragma unroll
                for (int j = 0; j < 8; ++j)
                    acc[i][j] = fmaf(aa[i], bb[j], acc[i][j]);
        }
        if (kt + 1 < 16) stAB(nxt);
        __syncthreads();
    }

#pragma unroll
    for (int i = 0; i < 8; ++i) {
        float pac = 0.f;
#pragma unroll
        for (int j = 0; j < 8; ++j) {
            int c = cx * 8 + j;
            float f = fast_tanh(acc[i][j] + bf[c]);
            pac = fmaf(f, Wp[c], pac);
        }
        pbuf[ry * 8 + i][cx] = pac;
    }
    __syncthreads();
    if (t < 64) {
        float s = bp[0];
#pragma unroll
        for (int x = 0; x < 16; ++x) s += pbuf[t][x];
        out[mb * 64 + t] = 1.f / (1.f + __expf(-s));
    }
}

// ---------------------------------------------------------------------------
// w = softmax(k @ Mk^T) : 32 rows/CTA, 128 threads. COMPACT pitch-50 output.
// ---------------------------------------------------------------------------
__global__ __launch_bounds__(128) void wsoftmax_kernel(
    const float* __restrict__ K, const float* __restrict__ Mk,
    float* __restrict__ Wout)
{
    __shared__ float sm_k[32 * 132];
    __shared__ float sm_m[50 * 132];
    float4* kt4 = reinterpret_cast<float4*>(sm_k);
    float4* mk4 = reinterpret_cast<float4*>(sm_m);
    float*  lg  = sm_k;

    const int t  = threadIdx.x;
    const int bi = blockIdx.x;

    for (int e = t; e < 32 * 32; e += 128) {
        int rw = e >> 5, c4 = e & 31;
        kt4[rw * 33 + c4] =
            *reinterpret_cast<const float4*>(K + ((size_t)(bi * 32 + rw)) * 128 + c4 * 4);
    }
    for (int e = t; e < 50 * 32; e += 128) {
        int m = e >> 5, c4 = e & 31;
        mk4[m * 33 + c4] = *reinterpret_cast<const float4*>(Mk + (size_t)m * 128 + c4 * 4);
    }
    __syncthreads();

    const int row = t >> 2;
    const int mg  = t & 3;
    const int m0  = (mg < 2) ? mg * 13 : 26 + (mg - 2) * 12;
    const int cnt = (mg < 2) ? 13 : 12;

    float s[13];
#pragma unroll
    for (int j = 0; j < 13; j++) s[j] = 0.f;

    for (int c4 = 0; c4 < 32; ++c4) {
        float4 kv = kt4[row * 33 + c4];
#pragma unroll
        for (int j = 0; j < 13; j++) {
            if (j < cnt) {
                float4 mv = mk4[(m0 + j) * 33 + c4];
                s[j] = fmaf(kv.x, mv.x, fmaf(kv.y, mv.y,
                        fmaf(kv.z, mv.z, fmaf(kv.w, mv.w, s[j]))));
            }
        }
    }
    __syncthreads();
#pragma unroll
    for (int j = 0; j < 13; j++)
        if (j < cnt) lg[row * 52 + m0 + j] = s[j];
    __syncthreads();

    if (t < 32) {
        float mx = -1e30f;
        for (int m = 0; m < 50; m++) mx = fmaxf(mx, lg[t * 52 + m]);
        float sum = 0.f;
        for (int m = 0; m < 50; m++) sum += __expf(lg[t * 52 + m] - mx);
        float inv = 1.f / sum;
        size_t ob = (size_t)(bi * 32 + t) * 50;
        for (int m = 0; m < 50; m++)
            Wout[ob + m] = __expf(lg[t * 52 + m] - mx) * inv;
    }
}

// ---------------------------------------------------------------------------
// Scan: CTA = batch (64 CTAs, 128 threads). Lane owns d and all 50 Mv in
// registers; whole 200x50 w block staged in smem (uniform LDS broadcasts).
// No barriers / reductions in the time loop. E/A prefetched 1 step ahead.
// ---------------------------------------------------------------------------
__global__ __launch_bounds__(128) void scan_kernel(
    const float* __restrict__ Wm, const float* __restrict__ E,
    const float* __restrict__ Aa, const float* __restrict__ Mv0,
    float* __restrict__ R)
{
    __shared__ float ws[200 * 50];    // 40 KB

    const int b = blockIdx.x;
    const int d = threadIdx.x;

    {
        const float4* src = reinterpret_cast<const float4*>(Wm + (size_t)b * 10000);
        float4* dst = reinterpret_cast<float4*>(ws);
        for (int i = d; i < 2500; i += 128) dst[i] = src[i];
    }

    float mv[50];
#pragma unroll
    for (int m = 0; m < 50; ++m) mv[m] = Mv0[m * 128 + d];
    __syncthreads();

    const size_t rowbase = (size_t)b * 200;
    const float* Ep = E  + rowbase * 128 + d;
    const float* Ap = Aa + rowbase * 128 + d;
    float*       Rp = R  + rowbase * 128 + d;

    float ed = Ep[0];
    float ad = Ap[0];

#pragma unroll 2
    for (int tt = 0; tt < 200; ++tt) {
        float en = 0.f, an = 0.f;
        if (tt < 199) {
            en = Ep[(size_t)(tt + 1) * 128];
            an = Ap[(size_t)(tt + 1) * 128];
        }

        const float* wrow = ws + tt * 50;
        float ac0 = 0.f, ac1 = 0.f, ac2 = 0.f, ac3 = 0.f;
#pragma unroll
        for (int m = 0; m < 50; ++m) {
            float wm = wrow[m];
            float mvm = mv[m];
            if ((m & 3) == 0)      ac0 = fmaf(wm, mvm, ac0);
            else if ((m & 3) == 1) ac1 = fmaf(wm, mvm, ac1);
            else if ((m & 3) == 2) ac2 = fmaf(wm, mvm, ac2);
            else                   ac3 = fmaf(wm, mvm, ac3);
            mv[m] = fmaf(wm, fmaf(-mvm, ed, ad), mvm);
        }
        Rp[(size_t)tt * 128] = (ac0 + ac1) + (ac2 + ac3);

        ed = en; ad = an;
    }
}

// ---------------------------------------------------------------------------
extern "C" void kernel_launch(void* const* d_in, const int* in_sizes, int n_in,
                              void* d_out, int out_size)
{
    const int*   q     = (const int*)d_in[0];
    const int*   r     = (const int*)d_in[1];
    // d_in[2] = diff (unused)
    const float* k_emb = (const float*)d_in[3];
    const float* v_emb = (const float*)d_in[4];
    const float* W1 = (const float*)d_in[5];
    const float* b1 = (const float*)d_in[6];
    const float* W2 = (const float*)d_in[7];
    const float* b2 = (const float*)d_in[8];
    const float* Mk  = (const float*)d_in[9];
    const float* Mv0 = (const float*)d_in[10];
    const float* We = (const float*)d_in[11];
    const float* be = (const float*)d_in[12];
    const float* Wa = (const float*)d_in[13];
    const float* ba = (const float*)d_in[14];
    const float* Wf = (const float*)d_in[15];
    const float* bf = (const float*)d_in[16];
    const float* Wp = (const float*)d_in[17];
    const float* bp = (const float*)d_in[18];
    float* out = (float*)d_out;

    float *pk, *pv, *pe, *pa, *pr, *pw;
    cudaGetSymbolAddress((void**)&pk, g_k);
    cudaGetSymbolAddress((void**)&pv, g_v);
    cudaGetSymbolAddress((void**)&pe, g_e);
    cudaGetSymbolAddress((void**)&pa, g_a);
    cudaGetSymbolAddress((void**)&pr, g_reads);
    cudaGetSymbolAddress((void**)&pw, g_w);

    kv_kernel<<<dim3(2, 200, 2), 64>>>(k_emb, v_emb, q, r, W1, b1, W2, b2, pk, pv);
    wsoftmax_kernel<<<400, 128>>>(pk, Mk, pw);
    ea_kernel<<<dim3(2, 200, 2), 64>>>(pv, We, be, Wa, ba, pe, pa);
    scan_kernel<<<64, 128>>>(pw, pe, pa, Mv0, pr);
    head_kernel<<<200, 128>>>(pr, pk, Wf, bf, Wp, bp, out);
}

// round 10
// speedup vs baseline: 1.6793x; 1.0385x over previous
#include <cuda_runtime.h>
#include <cuda_bf16.h>
#include <math.h>

// ---------------------------------------------------------------------------
// DKVMN: B=64, L=200, D=128, M=50, FIX=512. Rows = 12800.
//   kv_kernel (z=0): k = k_emb[q]@W1+b1        (z=1): v = v_emb[q+1e4r]@W2+b2
//   wsoftmax : w = softmax(k@Mk^T)  (compact pitch-50)
//   ea_kernel (z=0): e = sigmoid(v@We+be)      (z=1): a = tanh(v@Wa+ba)
//   scan : grid (4 d-chunks, 64 b); lane group-of-4 splits m; w in smem;
//          shfl-only r-reduction, no barriers in time loop.
//   head : p = sigmoid(tanh([reads|k]@Wf+bf)@Wp+bp)
// ---------------------------------------------------------------------------

#define NROWS 12800

__device__ float g_k[NROWS * 128];
__device__ float g_v[NROWS * 128];
__device__ float g_e[NROWS * 128];
__device__ float g_a[NROWS * 128];
__device__ float g_reads[NROWS * 128];
__device__ float g_w[NROWS * 50];   // compact pitch 50

__device__ __forceinline__ float fast_tanh(float x) {
    float y;
    asm("tanh.approx.f32 %0, %1;" : "=f"(y) : "f"(x));
    return y;
}
__device__ __forceinline__ float fast_sig(float x) {
    return 0.5f * fast_tanh(0.5f * x) + 0.5f;
}

// ---------------------------------------------------------------------------
// Core 64x64 mainloop (device function). aptr[u]: row base pointers.
// ---------------------------------------------------------------------------
template <int NT>
__device__ __forceinline__ void mm_core(
    const float* const (&aptr)[4], const float* __restrict__ Wb,
    float (&acc)[8][8], float (*As)[16][68], float (*Bs)[16][68],
    int t, int c4, int r0)
{
    float4 ar[4], br[4];
    auto ldA = [&](int kt) {
#pragma unroll
        for (int u = 0; u < 4; ++u)
            ar[u] = *reinterpret_cast<const float4*>(aptr[u] + kt * 16 + c4 * 4);
    };
    auto ldB = [&](int kt) {
#pragma unroll
        for (int u = 0; u < 4; ++u) {
            int e = t + u * 64;
            int rr = e >> 4, cb = e & 15;
            br[u] = *reinterpret_cast<const float4*>(Wb + (size_t)(kt * 16 + rr) * 128 + cb * 4);
        }
    };
    auto stAB = [&](int buf) {
#pragma unroll
        for (int u = 0; u < 4; ++u) {
            int row = r0 + u * 16;
            As[buf][c4 * 4 + 0][row] = ar[u].x;
            As[buf][c4 * 4 + 1][row] = ar[u].y;
            As[buf][c4 * 4 + 2][row] = ar[u].z;
            As[buf][c4 * 4 + 3][row] = ar[u].w;
        }
#pragma unroll
        for (int u = 0; u < 4; ++u) {
            int e = t + u * 64;
            int rr = e >> 4, cb = e & 15;
            *reinterpret_cast<float4*>(&Bs[buf][rr][cb * 4]) = br[u];
        }
    };

    const int cx = t & 7, ry = t >> 3;

    ldA(0); ldB(0); stAB(0);
    __syncthreads();

#pragma unroll 1
    for (int kt = 0; kt < NT; ++kt) {
        const int cur = kt & 1, nxt = cur ^ 1;
        if (kt + 1 < NT) { ldA(kt + 1); ldB(kt + 1); }
#pragma unroll
        for (int kk = 0; kk < 16; ++kk) {
            float4 a0 = *reinterpret_cast<const float4*>(&As[cur][kk][ry * 8]);
            float4 a1 = *reinterpret_cast<const float4*>(&As[cur][kk][ry * 8 + 4]);
            float4 b0 = *reinterpret_cast<const float4*>(&Bs[cur][kk][cx * 8]);
            float4 b1 = *reinterpret_cast<const float4*>(&Bs[cur][kk][cx * 8 + 4]);
            float aa[8] = {a0.x, a0.y, a0.z, a0.w, a1.x, a1.y, a1.z, a1.w};
            float bb[8] = {b0.x, b0.y, b0.z, b0.w, b1.x, b1.y, b1.z, b1.w};
#pragma unroll
            for (int i = 0; i < 8; ++i)
#pragma unroll
                for (int j = 0; j < 8; ++j)
                    acc[i][j] = fmaf(aa[i], bb[j], acc[i][j]);
        }
        if (kt + 1 < NT) stAB(nxt);
        __syncthreads();
    }
}

// ---------------------------------------------------------------------------
// kv_kernel: grid (2, 200, 2). z=0: k path; z=1: v path. K=512 gather GEMM.
// ---------------------------------------------------------------------------
__global__ __launch_bounds__(64) void kv_kernel(
    const float* __restrict__ k_emb, const float* __restrict__ v_emb,
    const int* __restrict__ qi, const int* __restrict__ ri,
    const float* __restrict__ W1, const float* __restrict__ b1,
    const float* __restrict__ W2, const float* __restrict__ b2,
    float* __restrict__ gk, float* __restrict__ gv)
{
    __shared__ float As[2][16][68];
    __shared__ float Bs[2][16][68];

    const int t  = threadIdx.x;
    const int nb = blockIdx.x;
    const int mb = blockIdx.y;
    const int z  = blockIdx.z;
    const int cx = t & 7, ry = t >> 3;
    const int c4 = t & 3, r0 = t >> 2;

    const float* emb  = z ? v_emb : k_emb;
    const float* W    = z ? W2 : W1;
    const float* bias = z ? b2 : b1;
    float*       C    = z ? gv : gk;

    const float* aptr[4];
#pragma unroll
    for (int u = 0; u < 4; ++u) {
        int rr = mb * 64 + r0 + u * 16;
        size_t arow = (size_t)qi[rr];
        if (z) arow += (size_t)10000 * (size_t)ri[rr];
        aptr[u] = emb + arow * 512;
    }
    const float* Wb = W + nb * 64;

    float acc[8][8];
#pragma unroll
    for (int i = 0; i < 8; i++)
#pragma unroll
        for (int j = 0; j < 8; j++) acc[i][j] = 0.f;

    mm_core<32>(aptr, Wb, acc, As, Bs, t, c4, r0);

#pragma unroll
    for (int i = 0; i < 8; ++i) {
        size_t row = (size_t)(mb * 64 + ry * 8 + i);
        float o[8];
#pragma unroll
        for (int j = 0; j < 8; ++j)
            o[j] = acc[i][j] + bias[nb * 64 + cx * 8 + j];
        float* dst = C + row * 128 + nb * 64 + cx * 8;
        *reinterpret_cast<float4*>(dst)     = make_float4(o[0], o[1], o[2], o[3]);
        *reinterpret_cast<float4*>(dst + 4) = make_float4(o[4], o[5], o[6], o[7]);
    }
}

// ---------------------------------------------------------------------------
// ea_kernel: grid (2, 200, 2). z=0: e = sigmoid(v@We+be); z=1: a = tanh(v@Wa+ba)
// ---------------------------------------------------------------------------
__global__ __launch_bounds__(64) void ea_kernel(
    const float* __restrict__ V,
    const float* __restrict__ We, const float* __restrict__ be,
    const float* __restrict__ Wa, const float* __restrict__ ba,
    float* __restrict__ ge, float* __restrict__ ga)
{
    __shared__ float As[2][16][68];
    __shared__ float Bs[2][16][68];

    const int t  = threadIdx.x;
    const int nb = blockIdx.x;
    const int mb = blockIdx.y;
    const int z  = blockIdx.z;
    const int cx = t & 7, ry = t >> 3;
    const int c4 = t & 3, r0 = t >> 2;

    const float* W    = z ? Wa : We;
    const float* bias = z ? ba : be;
    float*       C    = z ? ga : ge;

    const float* aptr[4];
#pragma unroll
    for (int u = 0; u < 4; ++u) {
        int rr = mb * 64 + r0 + u * 16;
        aptr[u] = V + (size_t)rr * 128;
    }
    const float* Wb = W + nb * 64;

    float acc[8][8];
#pragma unroll
    for (int i = 0; i < 8; i++)
#pragma unroll
        for (int j = 0; j < 8; j++) acc[i][j] = 0.f;

    mm_core<8>(aptr, Wb, acc, As, Bs, t, c4, r0);

#pragma unroll
    for (int i = 0; i < 8; ++i) {
        size_t row = (size_t)(mb * 64 + ry * 8 + i);
        float o[8];
#pragma unroll
        for (int j = 0; j < 8; ++j) {
            float vv = acc[i][j] + bias[nb * 64 + cx * 8 + j];
            o[j] = z ? fast_tanh(vv) : fast_sig(vv);
        }
        float* dst = C + row * 128 + nb * 64 + cx * 8;
        *reinterpret_cast<float4*>(dst)     = make_float4(o[0], o[1], o[2], o[3]);
        *reinterpret_cast<float4*>(dst + 4) = make_float4(o[4], o[5], o[6], o[7]);
    }
}

// ---------------------------------------------------------------------------
// head: 64x128 tile, 128 threads, 8x8 per thread, K=256 ([reads|k] concat).
// ---------------------------------------------------------------------------
__global__ __launch_bounds__(128) void head_kernel(
    const float* __restrict__ reads, const float* __restrict__ k,
    const float* __restrict__ Wf, const float* __restrict__ bf,
    const float* __restrict__ Wp, const float* __restrict__ bp,
    float* __restrict__ out)
{
    __shared__ float As[2][16][68];
    __shared__ float Bs[2][16][132];
    __shared__ float pbuf[64][17];

    const int t  = threadIdx.x;
    const int mb = blockIdx.x;
    const int cx = t & 15;
    const int ry = t >> 4;
    const int lrow = t >> 1;
    const int c4b  = (t & 1) * 2;

    const float* aR = reads + (size_t)(mb * 64 + lrow) * 128;
    const float* aK = k     + (size_t)(mb * 64 + lrow) * 128;

    float4 ar[2], br[4];
    auto ldA = [&](int kt) {
#pragma unroll
        for (int u = 0; u < 2; ++u) {
            const float* base = (kt < 8) ? (aR + kt * 16) : (aK + (kt - 8) * 16);
            ar[u] = *reinterpret_cast<const float4*>(base + (c4b + u) * 4);
        }
    };
    auto ldB = [&](int kt) {
#pragma unroll
        for (int u = 0; u < 4; ++u) {
            int e = t + u * 128;
            int rr = e >> 5, cb = e & 31;
            br[u] = *reinterpret_cast<const float4*>(Wf + (size_t)(kt * 16 + rr) * 128 + cb * 4);
        }
    };
    auto stAB = [&](int buf) {
#pragma unroll
        for (int u = 0; u < 2; ++u) {
            int kkb = (c4b + u) * 4;
            As[buf][kkb + 0][lrow] = ar[u].x;
            As[buf][kkb + 1][lrow] = ar[u].y;
            As[buf][kkb + 2][lrow] = ar[u].z;
            As[buf][kkb + 3][lrow] = ar[u].w;
        }
#pragma unroll
        for (int u = 0; u < 4; ++u) {
            int e = t + u * 128;
            int rr = e >> 5, cb = e & 31;
            *reinterpret_cast<float4*>(&Bs[buf][rr][cb * 4]) = br[u];
        }
    };

    float acc[8][8];
#pragma unroll
    for (int i = 0; i < 8; i++)
#pragma unroll
        for (int j = 0; j < 8; j++) acc[i][j] = 0.f;

    ldA(0); ldB(0); stAB(0);
    __syncthreads();

#pragma unroll 1
    for (int kt = 0; kt < 16; ++kt) {
        const int cur = kt & 1, nxt = cur ^ 1;
        if (kt + 1 < 16) { ldA(kt + 1); ldB(kt + 1); }
#pragma unroll
        for (int kk = 0; kk < 16; ++kk) {
            float4 a0 = *reinterpret_cast<const float4*>(&As[cur][kk][ry * 8]);
            float4 a1 = *reinterpret_cast<const float4*>(&As[cur][kk][ry * 8 + 4]);
            float4 b0 = *reinterpret_cast<const float4*>(&Bs[cur][kk][cx * 8]);
            float4 b1 = *reinterpret_cast<const float4*>(&Bs[cur][kk][cx * 8 + 4]);
            float aa[8] = {a0.x, a0.y, a0.z, a0.w, a1.x, a1.y, a1.z, a1.w};
            float bb[8] = {b0.x, b0.y, b0.z, b0.w, b1.x, b1.y, b1.z, b1.w};
#pragma unroll
            for (int i = 0; i < 8; ++i)
#pragma unroll
                for (int j = 0; j < 8; ++j)
                    acc[i][j] = fmaf(aa[i], bb[j], acc[i][j]);
        }
        if (kt + 1 < 16) stAB(nxt);
        __syncthreads();
    }

#pragma unroll
    for (int i = 0; i < 8; ++i) {
        float pac = 0.f;
#pragma unroll
        for (int j = 0; j < 8; ++j) {
            int c = cx * 8 + j;
            float f = fast_tanh(acc[i][j] + bf[c]);
            pac = fmaf(f, Wp[c], pac);
        }
        pbuf[ry * 8 + i][cx] = pac;
    }
    __syncthreads();
    if (t < 64) {
        float s = bp[0];
#pragma unroll
        for (int x = 0; x < 16; ++x) s += pbuf[t][x];
        out[mb * 64 + t] = 1.f / (1.f + __expf(-s));
    }
}

// ---------------------------------------------------------------------------
// w = softmax(k @ Mk^T) : 32 rows/CTA, 128 threads. COMPACT pitch-50 output.
// ---------------------------------------------------------------------------
__global__ __launch_bounds__(128) void wsoftmax_kernel(
    const float* __restrict__ K, const float* __restrict__ Mk,
    float* __restrict__ Wout)
{
    __shared__ float sm_k[32 * 132];
    __shared__ float sm_m[50 * 132];
    float4* kt4 = reinterpret_cast<float4*>(sm_k);
    float4* mk4 = reinterpret_cast<float4*>(sm_m);
    float*  lg  = sm_k;

    const int t  = threadIdx.x;
    const int bi = blockIdx.x;

    for (int e = t; e < 32 * 32; e += 128) {
        int rw = e >> 5, c4 = e & 31;
        kt4[rw * 33 + c4] =
            *reinterpret_cast<const float4*>(K + ((size_t)(bi * 32 + rw)) * 128 + c4 * 4);
    }
    for (int e = t; e < 50 * 32; e += 128) {
        int m = e >> 5, c4 = e & 31;
        mk4[m * 33 + c4] = *reinterpret_cast<const float4*>(Mk + (size_t)m * 128 + c4 * 4);
    }
    __syncthreads();

    const int row = t >> 2;
    const int mg  = t & 3;
    const int m0  = (mg < 2) ? mg * 13 : 26 + (mg - 2) * 12;
    const int cnt = (mg < 2) ? 13 : 12;

    float s[13];
#pragma unroll
    for (int j = 0; j < 13; j++) s[j] = 0.f;

    for (int c4 = 0; c4 < 32; ++c4) {
        float4 kv = kt4[row * 33 + c4];
#pragma unroll
        for (int j = 0; j < 13; j++) {
            if (j < cnt) {
                float4 mv = mk4[(m0 + j) * 33 + c4];
                s[j] = fmaf(kv.x, mv.x, fmaf(kv.y, mv.y,
                        fmaf(kv.z, mv.z, fmaf(kv.w, mv.w, s[j]))));
            }
        }
    }
    __syncthreads();
#pragma unroll
    for (int j = 0; j < 13; j++)
        if (j < cnt) lg[row * 52 + m0 + j] = s[j];
    __syncthreads();

    if (t < 32) {
        float mx = -1e30f;
        for (int m = 0; m < 50; m++) mx = fmaxf(mx, lg[t * 52 + m]);
        float sum = 0.f;
        for (int m = 0; m < 50; m++) sum += __expf(lg[t * 52 + m] - mx);
        float inv = 1.f / sum;
        size_t ob = (size_t)(bi * 32 + t) * 50;
        for (int m = 0; m < 50; m++)
            Wout[ob + m] = __expf(lg[t * 52 + m] - mx) * inv;
    }
}

// ---------------------------------------------------------------------------
// Scan: grid (4 d-chunks, 64 batches), 128 threads. Lane group-of-4:
// d = dc*32 + (t>>2), mq = t&3 owns 12-13 of the 50 Mv rows in registers.
// w staged in smem (uniform LDS). r_t closed by 2 shfl_xor within the
// group-of-4 (off the recurrence path). No barriers in the time loop.
// ---------------------------------------------------------------------------
__global__ __launch_bounds__(128) void scan_kernel(
    const float* __restrict__ Wm, const float* __restrict__ E,
    const float* __restrict__ Aa, const float* __restrict__ Mv0,
    float* __restrict__ R)
{
    __shared__ float ws[200 * 50];    // 40 KB

    const int dc = blockIdx.x;
    const int b  = blockIdx.y;
    const int t  = threadIdx.x;
    const int mq = t & 3;
    const int d  = dc * 32 + (t >> 2);
    const int m0  = (mq < 2) ? mq * 13 : 26 + (mq - 2) * 12;
    const int cnt = (mq < 2) ? 13 : 12;

    // stage w for this batch: 10000 floats = 2500 float4
    {
        const float4* src = reinterpret_cast<const float4*>(Wm + (size_t)b * 10000);
        float4* dst = reinterpret_cast<float4*>(ws);
        for (int i = t; i < 2500; i += 128) dst[i] = src[i];
    }

    float mv[13];
#pragma unroll
    for (int i = 0; i < 13; ++i)
        if (i < cnt) mv[i] = Mv0[(m0 + i) * 128 + d];
    __syncthreads();

    const size_t rowbase = (size_t)b * 200;
    const float* Ep = E  + rowbase * 128 + d;
    const float* Ap = Aa + rowbase * 128 + d;
    float*       Rp = R  + rowbase * 128 + d;

    float ed = Ep[0];
    float ad = Ap[0];

#pragma unroll 2
    for (int tt = 0; tt < 200; ++tt) {
        float en = 0.f, an = 0.f;
        if (tt < 199) {
            en = Ep[(size_t)(tt + 1) * 128];
            an = Ap[(size_t)(tt + 1) * 128];
        }

        const float* wrow = ws + tt * 50;
        float ac0 = 0.f, ac1 = 0.f;
#pragma unroll
        for (int i = 0; i < 13; ++i) {
            if (i < cnt) {
                float wm = wrow[m0 + i];
                float mvm = mv[i];
                if (i & 1) ac1 = fmaf(wm, mvm, ac1);
                else       ac0 = fmaf(wm, mvm, ac0);
                mv[i] = fmaf(wm, fmaf(-mvm, ed, ad), mvm);
            }
        }
        float partial = ac0 + ac1;
        partial += __shfl_xor_sync(0xffffffffu, partial, 1);
        partial += __shfl_xor_sync(0xffffffffu, partial, 2);
        if (mq == 0) Rp[(size_t)tt * 128] = partial;

        ed = en; ad = an;
    }
}

// ---------------------------------------------------------------------------
extern "C" void kernel_launch(void* const* d_in, const int* in_sizes, int n_in,
                              void* d_out, int out_size)
{
    const int*   q     = (const int*)d_in[0];
    const int*   r     = (const int*)d_in[1];
    // d_in[2] = diff (unused)
    const float* k_emb = (const float*)d_in[3];
    const float* v_emb = (const float*)d_in[4];
    const float* W1 = (const float*)d_in[5];
    const float* b1 = (const float*)d_in[6];
    const float* W2 = (const float*)d_in[7];
    const float* b2 = (const float*)d_in[8];
    const float* Mk  = (const float*)d_in[9];
    const float* Mv0 = (const float*)d_in[10];
    const float* We = (const float*)d_in[11];
    const float* be = (const float*)d_in[12];
    const float* Wa = (const float*)d_in[13];
    const float* ba = (const float*)d_in[14];
    const float* Wf = (const float*)d_in[15];
    const float* bf = (const float*)d_in[16];
    const float* Wp = (const float*)d_in[17];
    const float* bp = (const float*)d_in[18];
    float* out = (float*)d_out;

    float *pk, *pv, *pe, *pa, *pr, *pw;
    cudaGetSymbolAddress((void**)&pk, g_k);
    cudaGetSymbolAddress((void**)&pv, g_v);
    cudaGetSymbolAddress((void**)&pe, g_e);
    cudaGetSymbolAddress((void**)&pa, g_a);
    cudaGetSymbolAddress((void**)&pr, g_reads);
    cudaGetSymbolAddress((void**)&pw, g_w);

    kv_kernel<<<dim3(2, 200, 2), 64>>>(k_emb, v_emb, q, r, W1, b1, W2, b2, pk, pv);
    wsoftmax_kernel<<<400, 128>>>(pk, Mk, pw);
    ea_kernel<<<dim3(2, 200, 2), 64>>>(pv, We, be, Wa, ba, pe, pa);
    scan_kernel<<<dim3(4, 64), 128>>>(pw, pe, pa, Mv0, pr);
    head_kernel<<<200, 128>>>(pr, pk, Wf, bf, Wp, bp, out);
}